// round 14
// baseline (speedup 1.0000x reference)
#include <cuda_runtime.h>
#include <cuda_fp16.h>

// Problem shapes (fixed by the dataset)
#define BSZ  8
#define ENL  512   // encoder length
#define DEL  64    // decoder length
#define EDIM 512   // embedding
#define UDIM 512   // units
#define TDIM 100   // topics
#define STRIP 8    // strip depth in fused kernel

// Scratch (no cudaMalloc allowed)
__device__ __half g_aeT[BSZ * UDIM * ENL];  // att_en transposed: [b][u][i] (fp16, 4 MB)
__device__ float  g_c  [BSZ * DEL * UDIM];  // att_de + topic bias: [b][j][u] (1 MB)

typedef unsigned long long ull;

__device__ __forceinline__ ull pack2(float x, float y) {
    ull r; asm("mov.b64 %0, {%1, %2};" : "=l"(r) : "f"(x), "f"(y)); return r;
}
__device__ __forceinline__ void unpack2(ull p, float& x, float& y) {
    asm("mov.b64 {%0, %1}, %2;" : "=f"(x), "=f"(y) : "l"(p));
}
__device__ __forceinline__ ull fma2(ull a, ull b, ull c) {
    ull d; asm("fma.rn.f32x2 %0, %1, %2, %3;" : "=l"(d) : "l"(a), "l"(b), "l"(c));
    return d;
}
__device__ __forceinline__ unsigned cvt_f16x2(float lo, float hi) {
    unsigned p;
    asm("cvt.rn.f16x2.f32 %0, %1, %2;" : "=r"(p) : "f"(hi), "f"(lo));
    return p;
}
__device__ __forceinline__ __half2 htanh2(__half2 x) {
    unsigned xi = *reinterpret_cast<unsigned*>(&x), r;
    asm("tanh.approx.f16x2 %0, %1;" : "=r"(r) : "r"(xi));
    return *reinterpret_cast<__half2*>(&r);
}
__device__ __forceinline__ unsigned f2tf(float f) {
    unsigned r;
    asm("cvt.rna.tf32.f32 %0, %1;" : "=r"(r) : "f"(f));
    return r;
}
__device__ __forceinline__ void mma_tf32(
    float& c0, float& c1, float& c2, float& c3,
    unsigned a0, unsigned a1, unsigned a2, unsigned a3,
    unsigned b0, unsigned b1)
{
    asm volatile(
        "mma.sync.aligned.m16n8k8.row.col.f32.tf32.tf32.f32 "
        "{%0,%1,%2,%3}, {%4,%5,%6,%7}, {%8,%9}, {%0,%1,%2,%3};"
        : "+f"(c0), "+f"(c1), "+f"(c2), "+f"(c3)
        : "r"(a0), "r"(a1), "r"(a2), "r"(a3), "r"(b0), "r"(b1));
}

// ---------------------------------------------------------------------------
// Merged kernel: blocks x<32 run the tf32 tensor-core GEMM for g_aeT;
// blocks x in [32,40) run the FFMA2 k_c (de @ w_de + topic bias).
// The two are data-independent; merging removes serial latency + launch gap.
// grid = (40, BSZ). blockIdx.y = batch.
// ---------------------------------------------------------------------------
__global__ void __launch_bounds__(256, 2) k_gemm_c(
    const float* __restrict__ en, const float* __restrict__ w_en,
    const float* __restrict__ de, const float* __restrict__ w_de,
    const float* __restrict__ topics, const float* __restrict__ wt)
{
    const int b   = blockIdx.y;
    const int tid = threadIdx.x;

    if (blockIdx.x < 32) {
        // ===== tf32 GEMM: g_aeT[b][u][i] = (half) sum_e en[b][i][e]*w_en[e][u]
        const int u0 = (blockIdx.x >> 3) * 128;
        const int i0 = (blockIdx.x & 7) * 64;

        __shared__ unsigned As[2][16][136];  // [e][u] tf32
        __shared__ unsigned Bs[2][64][20];   // [i][e] tf32

        const int lane = tid & 31;
        const int warp = tid >> 5;
        const int wu = warp & 3;
        const int wi = warp >> 2;

        const int au4 = (tid & 31) * 4;
        const int ae_ = tid >> 5;
        const int bi  = tid >> 2;
        const int be4 = (tid & 3) * 4;

        const float* pa = w_en + (size_t)ae_ * UDIM + u0 + au4;
        const float* pb = en + ((size_t)b * ENL + i0 + bi) * EDIM + be4;

        float c[2][4][4];
        #pragma unroll
        for (int mf = 0; mf < 2; mf++)
            #pragma unroll
            for (int nf = 0; nf < 4; nf++)
                #pragma unroll
                for (int r = 0; r < 4; r++) c[mf][nf][r] = 0.f;

        #pragma unroll
        for (int p = 0; p < 2; p++) {
            float4 v = *(const float4*)(pa + (size_t)(8 * p) * UDIM);
            uint4 w = make_uint4(f2tf(v.x), f2tf(v.y), f2tf(v.z), f2tf(v.w));
            *(uint4*)&As[0][ae_ + 8 * p][au4] = w;
        }
        {
            float4 v = *(const float4*)pb;
            uint4 w = make_uint4(f2tf(v.x), f2tf(v.y), f2tf(v.z), f2tf(v.w));
            *(uint4*)&Bs[0][bi][be4] = w;
        }
        __syncthreads();

        int s = 0;
        for (int t = 0; t < 32; t++) {
            float4 ra[2], rb;
            if (t < 31) {
                const float* qa = pa + (size_t)(t + 1) * 16 * UDIM;
                const float* qb = pb + (t + 1) * 16;
                #pragma unroll
                for (int p = 0; p < 2; p++)
                    ra[p] = *(const float4*)(qa + (size_t)(8 * p) * UDIM);
                rb = *(const float4*)qb;
            }

            #pragma unroll
            for (int k8 = 0; k8 < 2; k8++) {
                const int e0 = k8 * 8 + (lane & 3);
                const int rA = wu * 32 + (lane >> 2);
                unsigned a[2][4];
                #pragma unroll
                for (int mf = 0; mf < 2; mf++) {
                    int row = rA + mf * 16;
                    a[mf][0] = As[s][e0    ][row    ];
                    a[mf][1] = As[s][e0    ][row + 8];
                    a[mf][2] = As[s][e0 + 4][row    ];
                    a[mf][3] = As[s][e0 + 4][row + 8];
                }
                unsigned bfr[4][2];
                const int cI = wi * 32 + (lane >> 2);
                #pragma unroll
                for (int nf = 0; nf < 4; nf++) {
                    int col = cI + nf * 8;
                    bfr[nf][0] = Bs[s][col][e0    ];
                    bfr[nf][1] = Bs[s][col][e0 + 4];
                }
                #pragma unroll
                for (int mf = 0; mf < 2; mf++)
                    #pragma unroll
                    for (int nf = 0; nf < 4; nf++)
                        mma_tf32(c[mf][nf][0], c[mf][nf][1], c[mf][nf][2], c[mf][nf][3],
                                 a[mf][0], a[mf][1], a[mf][2], a[mf][3],
                                 bfr[nf][0], bfr[nf][1]);
            }

            if (t < 31) {
                #pragma unroll
                for (int p = 0; p < 2; p++) {
                    uint4 w = make_uint4(f2tf(ra[p].x), f2tf(ra[p].y),
                                         f2tf(ra[p].z), f2tf(ra[p].w));
                    *(uint4*)&As[s ^ 1][ae_ + 8 * p][au4] = w;
                }
                uint4 w = make_uint4(f2tf(rb.x), f2tf(rb.y), f2tf(rb.z), f2tf(rb.w));
                *(uint4*)&Bs[s ^ 1][bi][be4] = w;
            }
            __syncthreads();
            s ^= 1;
        }

        __half* outb = g_aeT + (size_t)b * UDIM * ENL;
        #pragma unroll
        for (int mf = 0; mf < 2; mf++) {
            const int ug = u0 + wu * 32 + mf * 16 + (lane >> 2);
            #pragma unroll
            for (int nf = 0; nf < 4; nf++) {
                const int ig = i0 + wi * 32 + nf * 8 + 2 * (lane & 3);
                *(unsigned*)(outb + (size_t)ug * ENL + ig) =
                    cvt_f16x2(c[mf][nf][0], c[mf][nf][1]);
                *(unsigned*)(outb + (size_t)(ug + 8) * ENL + ig) =
                    cvt_f16x2(c[mf][nf][2], c[mf][nf][3]);
            }
        }
    } else {
        // ===== k_c: g_c[b][j][u] = sum_e de[b][j][e]*w_de[e][u] + tw[b][u]
        const int u0 = (blockIdx.x - 32) * 64;
        __shared__ float Ac[16][68];   // [e][j]
        __shared__ float Bc[16][68];   // [e][u]
        __shared__ float tws[64];
        const float* deb = de + (size_t)b * DEL * EDIM;
        const int tj = tid & 15;
        const int tu = tid >> 4;
        ull acc2[4][2] = {};

        if (tid < 64) {
            float acc = 0.f;
            const float* wr = wt + (size_t)(u0 + tid) * TDIM;
            const float* tp = topics + b * TDIM;
            #pragma unroll 4
            for (int t = 0; t < TDIM; t++) acc = fmaf(tp[t], wr[t], acc);
            tws[tid] = acc;
        }

        for (int e0 = 0; e0 < EDIM; e0 += 16) {
            #pragma unroll
            for (int r = 0; r < 4; r++) {
                int l = tid + 256 * r;
                int e = l & 15, j = l >> 4;
                Ac[e][j] = deb[(size_t)j * EDIM + e0 + e];
            }
            #pragma unroll
            for (int r = 0; r < 4; r++) {
                int l = tid + 256 * r;
                int e = l >> 6, uu = l & 63;
                Bc[e][uu] = w_de[(size_t)(e0 + e) * UDIM + u0 + uu];
            }
            __syncthreads();
            #pragma unroll
            for (int k = 0; k < 16; k++) {
                const float4 av = *(const float4*)&Ac[k][tj * 4];
                const ull b01 = *(const ull*)&Bc[k][tu * 4];
                const ull b23 = *(const ull*)&Bc[k][tu * 4 + 2];
                ull pa0 = pack2(av.x, av.x), pa1 = pack2(av.y, av.y);
                ull pa2 = pack2(av.z, av.z), pa3 = pack2(av.w, av.w);
                acc2[0][0] = fma2(pa0, b01, acc2[0][0]); acc2[0][1] = fma2(pa0, b23, acc2[0][1]);
                acc2[1][0] = fma2(pa1, b01, acc2[1][0]); acc2[1][1] = fma2(pa1, b23, acc2[1][1]);
                acc2[2][0] = fma2(pa2, b01, acc2[2][0]); acc2[2][1] = fma2(pa2, b23, acc2[2][1]);
                acc2[3][0] = fma2(pa3, b01, acc2[3][0]); acc2[3][1] = fma2(pa3, b23, acc2[3][1]);
            }
            __syncthreads();
        }
        #pragma unroll
        for (int r = 0; r < 4; r++) {
            float2 v01, v23;
            unpack2(acc2[r][0], v01.x, v01.y);
            unpack2(acc2[r][1], v23.x, v23.y);
            int j = tj * 4 + r;
            float* row = g_c + ((size_t)b * DEL + j) * UDIM + u0 + tu * 4;
            row[0] = v01.x + tws[tu * 4 + 0];
            row[1] = v01.y + tws[tu * 4 + 1];
            row[2] = v23.x + tws[tu * 4 + 2];
            row[3] = v23.y + tws[tu * 4 + 3];
        }
    }
}

// ---------------------------------------------------------------------------
// Kernel 3 (fused attention): block = (b, j0..j0+3), 1024 threads.
// (unchanged from R13)
// ---------------------------------------------------------------------------
__global__ void __launch_bounds__(1024, 1) k_attn(
    const float* __restrict__ en, const float* __restrict__ de,
    const float* __restrict__ nu, float* __restrict__ out)
{
    const int b   = blockIdx.y;
    const int j0  = blockIdx.x * 4;
    const int tid = threadIdx.x;
    const int q   = tid >> 8;
    const int tq  = tid & 255;

    __shared__ uint2 css[4][UDIM];
    __shared__ float alph_s[ENL][4];
    __shared__ float redq[4][8];

    {
        const float* cb = g_c + ((size_t)b * DEL + j0 + q) * UDIM;
        #pragma unroll
        for (int uu = tq; uu < UDIM; uu += 256) {
            float cv = cb[uu];
            __half2 ch = __float2half2_rn(cv);
            css[q][uu] = make_uint2(*reinterpret_cast<unsigned*>(&ch),
                                    __float_as_uint(nu[uu]));
        }
    }
    __syncthreads();

    const __half2* ae = reinterpret_cast<const __half2*>(
                            g_aeT + (size_t)b * UDIM * ENL) + tq;
    float m0 = 0.f, m1 = 0.f;
    {
        __half2 bufA[STRIP], bufB[STRIP];
        #pragma unroll
        for (int k = 0; k < STRIP; k++)
            bufA[k] = __ldg(ae + (size_t)k * (ENL / 2));

        #pragma unroll 1
        for (int u0 = 0; u0 < UDIM; u0 += 2 * STRIP) {
            #pragma unroll
            for (int k = 0; k < STRIP; k++)
                bufB[k] = __ldg(ae + (size_t)(u0 + STRIP + k) * (ENL / 2));
            #pragma unroll
            for (int k = 0; k < STRIP; k++) {
                uint2 cn = css[q][u0 + k];
                __half2 ch = *reinterpret_cast<__half2*>(&cn.x);
                float nv = __uint_as_float(cn.y);
                float2 tf = __half22float2(htanh2(__hadd2(bufA[k], ch)));
                m0 = fmaf(nv, tf.x, m0);
                m1 = fmaf(nv, tf.y, m1);
            }
            if (u0 + 2 * STRIP < UDIM) {
                #pragma unroll
                for (int k = 0; k < STRIP; k++)
                    bufA[k] = __ldg(ae + (size_t)(u0 + 2 * STRIP + k) * (ENL / 2));
            }
            #pragma unroll
            for (int k = 0; k < STRIP; k++) {
                uint2 cn = css[q][u0 + STRIP + k];
                __half2 ch = *reinterpret_cast<__half2*>(&cn.x);
                float nv = __uint_as_float(cn.y);
                float2 tf = __half22float2(htanh2(__hadd2(bufB[k], ch)));
                m0 = fmaf(nv, tf.x, m0);
                m1 = fmaf(nv, tf.y, m1);
            }
        }
    }

    float e0 = __expf(m0);
    float e1 = __expf(m1);

    const int widq = tq >> 5, lane = tq & 31;
    float sum = e0 + e1;
    #pragma unroll
    for (int o = 16; o; o >>= 1)
        sum += __shfl_xor_sync(0xffffffffu, sum, o);
    if (lane == 0) redq[q][widq] = sum;
    __syncthreads();
    float S = redq[q][0];
    #pragma unroll
    for (int w = 1; w < 8; w++) S += redq[q][w];

    float inv = 1.f / S;
    float a0 = e0 * inv, a1 = e1 * inv;
    alph_s[2 * tq][q]     = a0;
    alph_s[2 * tq + 1][q] = a1;

    float* alphas_out = out + BSZ * DEL * ENL;
    float* pgen_out   = out + 2 * BSZ * DEL * ENL;
    const int base = ((b * DEL + j0 + q) * ENL) + 2 * tq;
    *(float2*)(alphas_out + base) = make_float2(a0, a1);
    *(float2*)(pgen_out + base) =
        make_float2(1.f / (1.f + __expf(-m0)), 1.f / (1.f + __expf(-m1)));
    __syncthreads();

    const int half = tid >> 9;
    const int t    = tid & 511;
    float s0 = 0.f, s1 = 0.f;
    const float* enb = en + (size_t)b * ENL * EDIM + t;
    {
        float bufA[STRIP], bufB[STRIP];
        #pragma unroll
        for (int k = 0; k < STRIP; k++)
            bufA[k] = __ldg(enb + (size_t)k * EDIM);

        #pragma unroll 1
        for (int i0 = 0; i0 < ENL; i0 += 2 * STRIP) {
            #pragma unroll
            for (int k = 0; k < STRIP; k++)
                bufB[k] = __ldg(enb + (size_t)(i0 + STRIP + k) * EDIM);
            #pragma unroll
            for (int k = 0; k < STRIP; k++) {
                float2 av = *(const float2*)&alph_s[i0 + k][2 * half];
                s0 = fmaf(av.x, bufA[k], s0);
                s1 = fmaf(av.y, bufA[k], s1);
            }
            if (i0 + 2 * STRIP < ENL) {
                #pragma unroll
                for (int k = 0; k < STRIP; k++)
                    bufA[k] = __ldg(enb + (size_t)(i0 + 2 * STRIP + k) * EDIM);
            }
            #pragma unroll
            for (int k = 0; k < STRIP; k++) {
                float2 av = *(const float2*)&alph_s[i0 + STRIP + k][2 * half];
                s0 = fmaf(av.x, bufB[k], s0);
                s1 = fmaf(av.y, bufB[k], s1);
            }
        }
    }
    const int ob = ((b * DEL + j0 + 2 * half) * EDIM) + t;
    out[ob       ] = de[ob       ] + s0;
    out[ob + EDIM] = de[ob + EDIM] + s1;
}

// ---------------------------------------------------------------------------
extern "C" void kernel_launch(void* const* d_in, const int* in_sizes, int n_in,
                              void* d_out, int out_size)
{
    const float* en     = (const float*)d_in[0];
    const float* de     = (const float*)d_in[1];
    const float* topics = (const float*)d_in[2];
    const float* w_en   = (const float*)d_in[3];
    const float* w_de   = (const float*)d_in[4];
    const float* nu     = (const float*)d_in[5];
    const float* wt     = (const float*)d_in[6];
    float* out = (float*)d_out;

    k_gemm_c<<<dim3(40, BSZ), 256>>>(en, w_en, de, w_de, topics, wt);
    k_attn<<<dim3(DEL / 4, BSZ), 1024>>>(en, de, nu, out);
}

// round 15
// speedup vs baseline: 1.1022x; 1.1022x over previous
#include <cuda_runtime.h>
#include <cuda_fp16.h>

// Problem shapes (fixed by the dataset)
#define BSZ  8
#define ENL  512   // encoder length
#define DEL  64    // decoder length
#define EDIM 512   // embedding
#define UDIM 512   // units
#define TDIM 100   // topics
#define STRIP 8    // strip depth in fused kernel

// Scratch (no cudaMalloc allowed)
__device__ __half g_aeT[BSZ * UDIM * ENL];  // att_en transposed: [b][u][i] (fp16, 4 MB)
__device__ float  g_c  [BSZ * DEL * UDIM];  // att_de + topic bias: [b][j][u] (1 MB)

typedef unsigned long long ull;

__device__ __forceinline__ ull pack2(float x, float y) {
    ull r; asm("mov.b64 %0, {%1, %2};" : "=l"(r) : "f"(x), "f"(y)); return r;
}
__device__ __forceinline__ void unpack2(ull p, float& x, float& y) {
    asm("mov.b64 {%0, %1}, %2;" : "=f"(x), "=f"(y) : "l"(p));
}
__device__ __forceinline__ ull fma2(ull a, ull b, ull c) {
    ull d; asm("fma.rn.f32x2 %0, %1, %2, %3;" : "=l"(d) : "l"(a), "l"(b), "l"(c));
    return d;
}
__device__ __forceinline__ unsigned cvt_f16x2(float lo, float hi) {
    unsigned p;
    asm("cvt.rn.f16x2.f32 %0, %1, %2;" : "=r"(p) : "f"(hi), "f"(lo));
    return p;
}
__device__ __forceinline__ __half2 htanh2(__half2 x) {
    unsigned xi = *reinterpret_cast<unsigned*>(&x), r;
    asm("tanh.approx.f16x2 %0, %1;" : "=r"(r) : "r"(xi));
    return *reinterpret_cast<__half2*>(&r);
}
__device__ __forceinline__ unsigned f2tf(float f) {
    unsigned r;
    asm("cvt.rna.tf32.f32 %0, %1;" : "=r"(r) : "f"(f));
    return r;
}
__device__ __forceinline__ void mma_tf32(
    float& c0, float& c1, float& c2, float& c3,
    unsigned a0, unsigned a1, unsigned a2, unsigned a3,
    unsigned b0, unsigned b1)
{
    asm volatile(
        "mma.sync.aligned.m16n8k8.row.col.f32.tf32.tf32.f32 "
        "{%0,%1,%2,%3}, {%4,%5,%6,%7}, {%8,%9}, {%0,%1,%2,%3};"
        : "+f"(c0), "+f"(c1), "+f"(c2), "+f"(c3)
        : "r"(a0), "r"(a1), "r"(a2), "r"(a3), "r"(b0), "r"(b1));
}

// ---------------------------------------------------------------------------
// Merged kernel, SINGLE WAVE: grid (24, BSZ) = 192 blocks (< 296 capacity).
// blocks x<16: tf32 GEMM, 128u x 128i tiles (16 tiles/batch).
// blocks x in [16,24): FFMA2 k_c (de @ w_de + topic bias), hidden under gemm.
// ---------------------------------------------------------------------------
__global__ void __launch_bounds__(256, 2) k_gemm_c(
    const float* __restrict__ en, const float* __restrict__ w_en,
    const float* __restrict__ de, const float* __restrict__ w_de,
    const float* __restrict__ topics, const float* __restrict__ wt)
{
    const int b   = blockIdx.y;
    const int tid = threadIdx.x;

    if (blockIdx.x < 16) {
        // ===== tf32 GEMM: g_aeT[b][u][i] = (half) sum_e en[b][i][e]*w_en[e][u]
        const int u0 = (blockIdx.x >> 2) * 128;
        const int i0 = (blockIdx.x & 3) * 128;

        __shared__ unsigned As[2][16][136];  // [e][u] tf32
        __shared__ unsigned Bs[2][128][20];  // [i][e] tf32

        const int lane = tid & 31;
        const int warp = tid >> 5;
        const int wu = warp >> 2;      // 0..1, 64-u subtile
        const int wi = warp & 3;       // 0..3, 32-i subtile

        // A staging: 128u x 16e per stage; thread does 2 float4 (e and e+8)
        const int au4 = (tid & 31) * 4;
        const int ae_ = tid >> 5;
        // B staging: 128i x 16e; thread does 2 float4 at e = be4, be4+4
        const int bi  = tid >> 1;
        const int be4 = (tid & 1) * 8;

        const float* pa = w_en + (size_t)ae_ * UDIM + u0 + au4;
        const float* pb = en + ((size_t)b * ENL + i0 + bi) * EDIM + be4;

        float c[4][4][4];   // [mf 16u][nf 8i][frag]
        #pragma unroll
        for (int mf = 0; mf < 4; mf++)
            #pragma unroll
            for (int nf = 0; nf < 4; nf++)
                #pragma unroll
                for (int r = 0; r < 4; r++) c[mf][nf][r] = 0.f;

        // Prologue: stage tile 0
        #pragma unroll
        for (int p = 0; p < 2; p++) {
            float4 v = *(const float4*)(pa + (size_t)(8 * p) * UDIM);
            uint4 w = make_uint4(f2tf(v.x), f2tf(v.y), f2tf(v.z), f2tf(v.w));
            *(uint4*)&As[0][ae_ + 8 * p][au4] = w;
        }
        #pragma unroll
        for (int p = 0; p < 2; p++) {
            float4 v = *(const float4*)(pb + 4 * p);
            uint4 w = make_uint4(f2tf(v.x), f2tf(v.y), f2tf(v.z), f2tf(v.w));
            *(uint4*)&Bs[0][bi][be4 + 4 * p] = w;
        }
        __syncthreads();

        int s = 0;
        for (int t = 0; t < 32; t++) {
            float4 ra[2], rb[2];
            if (t < 31) {
                const float* qa = pa + (size_t)(t + 1) * 16 * UDIM;
                const float* qb = pb + (t + 1) * 16;
                #pragma unroll
                for (int p = 0; p < 2; p++)
                    ra[p] = *(const float4*)(qa + (size_t)(8 * p) * UDIM);
                #pragma unroll
                for (int p = 0; p < 2; p++)
                    rb[p] = *(const float4*)(qb + 4 * p);
            }

            #pragma unroll
            for (int k8 = 0; k8 < 2; k8++) {
                const int e0 = k8 * 8 + (lane & 3);
                unsigned a[4][4];
                #pragma unroll
                for (int mf = 0; mf < 4; mf++) {
                    int row = wu * 64 + mf * 16 + (lane >> 2);
                    a[mf][0] = As[s][e0    ][row    ];
                    a[mf][1] = As[s][e0    ][row + 8];
                    a[mf][2] = As[s][e0 + 4][row    ];
                    a[mf][3] = As[s][e0 + 4][row + 8];
                }
                unsigned bfr[4][2];
                #pragma unroll
                for (int nf = 0; nf < 4; nf++) {
                    int col = wi * 32 + nf * 8 + (lane >> 2);
                    bfr[nf][0] = Bs[s][col][e0    ];
                    bfr[nf][1] = Bs[s][col][e0 + 4];
                }
                #pragma unroll
                for (int mf = 0; mf < 4; mf++)
                    #pragma unroll
                    for (int nf = 0; nf < 4; nf++)
                        mma_tf32(c[mf][nf][0], c[mf][nf][1], c[mf][nf][2], c[mf][nf][3],
                                 a[mf][0], a[mf][1], a[mf][2], a[mf][3],
                                 bfr[nf][0], bfr[nf][1]);
            }

            if (t < 31) {
                #pragma unroll
                for (int p = 0; p < 2; p++) {
                    uint4 w = make_uint4(f2tf(ra[p].x), f2tf(ra[p].y),
                                         f2tf(ra[p].z), f2tf(ra[p].w));
                    *(uint4*)&As[s ^ 1][ae_ + 8 * p][au4] = w;
                }
                #pragma unroll
                for (int p = 0; p < 2; p++) {
                    uint4 w = make_uint4(f2tf(rb[p].x), f2tf(rb[p].y),
                                         f2tf(rb[p].z), f2tf(rb[p].w));
                    *(uint4*)&Bs[s ^ 1][bi][be4 + 4 * p] = w;
                }
            }
            __syncthreads();
            s ^= 1;
        }

        __half* outb = g_aeT + (size_t)b * UDIM * ENL;
        #pragma unroll
        for (int mf = 0; mf < 4; mf++) {
            const int ug = u0 + wu * 64 + mf * 16 + (lane >> 2);
            #pragma unroll
            for (int nf = 0; nf < 4; nf++) {
                const int ig = i0 + wi * 32 + nf * 8 + 2 * (lane & 3);
                *(unsigned*)(outb + (size_t)ug * ENL + ig) =
                    cvt_f16x2(c[mf][nf][0], c[mf][nf][1]);
                *(unsigned*)(outb + (size_t)(ug + 8) * ENL + ig) =
                    cvt_f16x2(c[mf][nf][2], c[mf][nf][3]);
            }
        }
    } else {
        // ===== k_c: g_c[b][j][u] = sum_e de[b][j][e]*w_de[e][u] + tw[b][u]
        const int u0 = (blockIdx.x - 16) * 64;
        __shared__ float Ac[16][68];   // [e][j]
        __shared__ float Bc[16][68];   // [e][u]
        __shared__ float tws[64];
        const float* deb = de + (size_t)b * DEL * EDIM;
        const int tj = tid & 15;
        const int tu = tid >> 4;
        ull acc2[4][2] = {};

        if (tid < 64) {
            float acc = 0.f;
            const float* wr = wt + (size_t)(u0 + tid) * TDIM;
            const float* tp = topics + b * TDIM;
            #pragma unroll 4
            for (int t = 0; t < TDIM; t++) acc = fmaf(tp[t], wr[t], acc);
            tws[tid] = acc;
        }

        for (int e0 = 0; e0 < EDIM; e0 += 16) {
            #pragma unroll
            for (int r = 0; r < 4; r++) {
                int l = tid + 256 * r;
                int e = l & 15, j = l >> 4;
                Ac[e][j] = deb[(size_t)j * EDIM + e0 + e];
            }
            #pragma unroll
            for (int r = 0; r < 4; r++) {
                int l = tid + 256 * r;
                int e = l >> 6, uu = l & 63;
                Bc[e][uu] = w_de[(size_t)(e0 + e) * UDIM + u0 + uu];
            }
            __syncthreads();
            #pragma unroll
            for (int k = 0; k < 16; k++) {
                const float4 av = *(const float4*)&Ac[k][tj * 4];
                const ull b01 = *(const ull*)&Bc[k][tu * 4];
                const ull b23 = *(const ull*)&Bc[k][tu * 4 + 2];
                ull pa0 = pack2(av.x, av.x), pa1 = pack2(av.y, av.y);
                ull pa2 = pack2(av.z, av.z), pa3 = pack2(av.w, av.w);
                acc2[0][0] = fma2(pa0, b01, acc2[0][0]); acc2[0][1] = fma2(pa0, b23, acc2[0][1]);
                acc2[1][0] = fma2(pa1, b01, acc2[1][0]); acc2[1][1] = fma2(pa1, b23, acc2[1][1]);
                acc2[2][0] = fma2(pa2, b01, acc2[2][0]); acc2[2][1] = fma2(pa2, b23, acc2[2][1]);
                acc2[3][0] = fma2(pa3, b01, acc2[3][0]); acc2[3][1] = fma2(pa3, b23, acc2[3][1]);
            }
            __syncthreads();
        }
        #pragma unroll
        for (int r = 0; r < 4; r++) {
            float2 v01, v23;
            unpack2(acc2[r][0], v01.x, v01.y);
            unpack2(acc2[r][1], v23.x, v23.y);
            int j = tj * 4 + r;
            float* row = g_c + ((size_t)b * DEL + j) * UDIM + u0 + tu * 4;
            row[0] = v01.x + tws[tu * 4 + 0];
            row[1] = v01.y + tws[tu * 4 + 1];
            row[2] = v23.x + tws[tu * 4 + 2];
            row[3] = v23.y + tws[tu * 4 + 3];
        }
    }
}

// ---------------------------------------------------------------------------
// Kernel 3 (fused attention): block = (b, j0..j0+3), 1024 threads.
// (unchanged from R13)
// ---------------------------------------------------------------------------
__global__ void __launch_bounds__(1024, 1) k_attn(
    const float* __restrict__ en, const float* __restrict__ de,
    const float* __restrict__ nu, float* __restrict__ out)
{
    const int b   = blockIdx.y;
    const int j0  = blockIdx.x * 4;
    const int tid = threadIdx.x;
    const int q   = tid >> 8;
    const int tq  = tid & 255;

    __shared__ uint2 css[4][UDIM];
    __shared__ float alph_s[ENL][4];
    __shared__ float redq[4][8];

    {
        const float* cb = g_c + ((size_t)b * DEL + j0 + q) * UDIM;
        #pragma unroll
        for (int uu = tq; uu < UDIM; uu += 256) {
            float cv = cb[uu];
            __half2 ch = __float2half2_rn(cv);
            css[q][uu] = make_uint2(*reinterpret_cast<unsigned*>(&ch),
                                    __float_as_uint(nu[uu]));
        }
    }
    __syncthreads();

    const __half2* ae = reinterpret_cast<const __half2*>(
                            g_aeT + (size_t)b * UDIM * ENL) + tq;
    float m0 = 0.f, m1 = 0.f;
    {
        __half2 bufA[STRIP], bufB[STRIP];
        #pragma unroll
        for (int k = 0; k < STRIP; k++)
            bufA[k] = __ldg(ae + (size_t)k * (ENL / 2));

        #pragma unroll 1
        for (int u0 = 0; u0 < UDIM; u0 += 2 * STRIP) {
            #pragma unroll
            for (int k = 0; k < STRIP; k++)
                bufB[k] = __ldg(ae + (size_t)(u0 + STRIP + k) * (ENL / 2));
            #pragma unroll
            for (int k = 0; k < STRIP; k++) {
                uint2 cn = css[q][u0 + k];
                __half2 ch = *reinterpret_cast<__half2*>(&cn.x);
                float nv = __uint_as_float(cn.y);
                float2 tf = __half22float2(htanh2(__hadd2(bufA[k], ch)));
                m0 = fmaf(nv, tf.x, m0);
                m1 = fmaf(nv, tf.y, m1);
            }
            if (u0 + 2 * STRIP < UDIM) {
                #pragma unroll
                for (int k = 0; k < STRIP; k++)
                    bufA[k] = __ldg(ae + (size_t)(u0 + 2 * STRIP + k) * (ENL / 2));
            }
            #pragma unroll
            for (int k = 0; k < STRIP; k++) {
                uint2 cn = css[q][u0 + STRIP + k];
                __half2 ch = *reinterpret_cast<__half2*>(&cn.x);
                float nv = __uint_as_float(cn.y);
                float2 tf = __half22float2(htanh2(__hadd2(bufB[k], ch)));
                m0 = fmaf(nv, tf.x, m0);
                m1 = fmaf(nv, tf.y, m1);
            }
        }
    }

    float e0 = __expf(m0);
    float e1 = __expf(m1);

    const int widq = tq >> 5, lane = tq & 31;
    float sum = e0 + e1;
    #pragma unroll
    for (int o = 16; o; o >>= 1)
        sum += __shfl_xor_sync(0xffffffffu, sum, o);
    if (lane == 0) redq[q][widq] = sum;
    __syncthreads();
    float S = redq[q][0];
    #pragma unroll
    for (int w = 1; w < 8; w++) S += redq[q][w];

    float inv = 1.f / S;
    float a0 = e0 * inv, a1 = e1 * inv;
    alph_s[2 * tq][q]     = a0;
    alph_s[2 * tq + 1][q] = a1;

    float* alphas_out = out + BSZ * DEL * ENL;
    float* pgen_out   = out + 2 * BSZ * DEL * ENL;
    const int base = ((b * DEL + j0 + q) * ENL) + 2 * tq;
    *(float2*)(alphas_out + base) = make_float2(a0, a1);
    *(float2*)(pgen_out + base) =
        make_float2(1.f / (1.f + __expf(-m0)), 1.f / (1.f + __expf(-m1)));
    __syncthreads();

    const int half = tid >> 9;
    const int t    = tid & 511;
    float s0 = 0.f, s1 = 0.f;
    const float* enb = en + (size_t)b * ENL * EDIM + t;
    {
        float bufA[STRIP], bufB[STRIP];
        #pragma unroll
        for (int k = 0; k < STRIP; k++)
            bufA[k] = __ldg(enb + (size_t)k * EDIM);

        #pragma unroll 1
        for (int i0 = 0; i0 < ENL; i0 += 2 * STRIP) {
            #pragma unroll
            for (int k = 0; k < STRIP; k++)
                bufB[k] = __ldg(enb + (size_t)(i0 + STRIP + k) * EDIM);
            #pragma unroll
            for (int k = 0; k < STRIP; k++) {
                float2 av = *(const float2*)&alph_s[i0 + k][2 * half];
                s0 = fmaf(av.x, bufA[k], s0);
                s1 = fmaf(av.y, bufA[k], s1);
            }
            if (i0 + 2 * STRIP < ENL) {
                #pragma unroll
                for (int k = 0; k < STRIP; k++)
                    bufA[k] = __ldg(enb + (size_t)(i0 + 2 * STRIP + k) * EDIM);
            }
            #pragma unroll
            for (int k = 0; k < STRIP; k++) {
                float2 av = *(const float2*)&alph_s[i0 + STRIP + k][2 * half];
                s0 = fmaf(av.x, bufB[k], s0);
                s1 = fmaf(av.y, bufB[k], s1);
            }
        }
    }
    const int ob = ((b * DEL + j0 + 2 * half) * EDIM) + t;
    out[ob       ] = de[ob       ] + s0;
    out[ob + EDIM] = de[ob + EDIM] + s1;
}

// ---------------------------------------------------------------------------
extern "C" void kernel_launch(void* const* d_in, const int* in_sizes, int n_in,
                              void* d_out, int out_size)
{
    const float* en     = (const float*)d_in[0];
    const float* de     = (const float*)d_in[1];
    const float* topics = (const float*)d_in[2];
    const float* w_en   = (const float*)d_in[3];
    const float* w_de   = (const float*)d_in[4];
    const float* nu     = (const float*)d_in[5];
    const float* wt     = (const float*)d_in[6];
    float* out = (float*)d_out;

    k_gemm_c<<<dim3(24, BSZ), 256>>>(en, w_en, de, w_de, topics, wt);
    k_attn<<<dim3(DEL / 4, BSZ), 1024>>>(en, de, nu, out);
}

// round 16
// speedup vs baseline: 1.1525x; 1.0457x over previous
#include <cuda_runtime.h>
#include <cuda_fp16.h>

// Problem shapes (fixed by the dataset)
#define BSZ  8
#define ENL  512   // encoder length
#define DEL  64    // decoder length
#define EDIM 512   // embedding
#define UDIM 512   // units
#define TDIM 100   // topics
#define STRIP 8    // strip depth in fused kernel

// Scratch (no cudaMalloc allowed)
__device__ __half g_aeT[BSZ * UDIM * ENL];  // att_en transposed: [b][u][i] (fp16, 4 MB)
__device__ float  g_c  [BSZ * DEL * UDIM];  // att_de + topic bias: [b][j][u] (1 MB)

typedef unsigned long long ull;

__device__ __forceinline__ ull pack2(float x, float y) {
    ull r; asm("mov.b64 %0, {%1, %2};" : "=l"(r) : "f"(x), "f"(y)); return r;
}
__device__ __forceinline__ void unpack2(ull p, float& x, float& y) {
    asm("mov.b64 {%0, %1}, %2;" : "=f"(x), "=f"(y) : "l"(p));
}
__device__ __forceinline__ ull fma2(ull a, ull b, ull c) {
    ull d; asm("fma.rn.f32x2 %0, %1, %2, %3;" : "=l"(d) : "l"(a), "l"(b), "l"(c));
    return d;
}
__device__ __forceinline__ unsigned cvt_f16x2(float lo, float hi) {
    unsigned p;
    asm("cvt.rn.f16x2.f32 %0, %1, %2;" : "=r"(p) : "f"(hi), "f"(lo));
    return p;
}
__device__ __forceinline__ __half2 htanh2(__half2 x) {
    unsigned xi = *reinterpret_cast<unsigned*>(&x), r;
    asm("tanh.approx.f16x2 %0, %1;" : "=r"(r) : "r"(xi));
    return *reinterpret_cast<__half2*>(&r);
}
__device__ __forceinline__ unsigned f2tf(float f) {
    unsigned r;
    asm("cvt.rna.tf32.f32 %0, %1;" : "=r"(r) : "f"(f));
    return r;
}
__device__ __forceinline__ void mma_tf32(
    float& c0, float& c1, float& c2, float& c3,
    unsigned a0, unsigned a1, unsigned a2, unsigned a3,
    unsigned b0, unsigned b1)
{
    asm volatile(
        "mma.sync.aligned.m16n8k8.row.col.f32.tf32.tf32.f32 "
        "{%0,%1,%2,%3}, {%4,%5,%6,%7}, {%8,%9}, {%0,%1,%2,%3};"
        : "+f"(c0), "+f"(c1), "+f"(c2), "+f"(c3)
        : "r"(a0), "r"(a1), "r"(a2), "r"(a3), "r"(b0), "r"(b1));
}

// ---------------------------------------------------------------------------
// Merged kernel, SINGLE WAVE (unchanged from R15): grid (24, BSZ) = 192 blocks.
// blocks x<16: tf32 GEMM, 128u x 128i tiles. blocks [16,24): FFMA2 k_c.
// ---------------------------------------------------------------------------
__global__ void __launch_bounds__(256, 2) k_gemm_c(
    const float* __restrict__ en, const float* __restrict__ w_en,
    const float* __restrict__ de, const float* __restrict__ w_de,
    const float* __restrict__ topics, const float* __restrict__ wt)
{
    const int b   = blockIdx.y;
    const int tid = threadIdx.x;

    if (blockIdx.x < 16) {
        const int u0 = (blockIdx.x >> 2) * 128;
        const int i0 = (blockIdx.x & 3) * 128;

        __shared__ unsigned As[2][16][136];  // [e][u] tf32
        __shared__ unsigned Bs[2][128][20];  // [i][e] tf32

        const int lane = tid & 31;
        const int warp = tid >> 5;
        const int wu = warp >> 2;
        const int wi = warp & 3;

        const int au4 = (tid & 31) * 4;
        const int ae_ = tid >> 5;
        const int bi  = tid >> 1;
        const int be4 = (tid & 1) * 8;

        const float* pa = w_en + (size_t)ae_ * UDIM + u0 + au4;
        const float* pb = en + ((size_t)b * ENL + i0 + bi) * EDIM + be4;

        float c[4][4][4];
        #pragma unroll
        for (int mf = 0; mf < 4; mf++)
            #pragma unroll
            for (int nf = 0; nf < 4; nf++)
                #pragma unroll
                for (int r = 0; r < 4; r++) c[mf][nf][r] = 0.f;

        #pragma unroll
        for (int p = 0; p < 2; p++) {
            float4 v = *(const float4*)(pa + (size_t)(8 * p) * UDIM);
            uint4 w = make_uint4(f2tf(v.x), f2tf(v.y), f2tf(v.z), f2tf(v.w));
            *(uint4*)&As[0][ae_ + 8 * p][au4] = w;
        }
        #pragma unroll
        for (int p = 0; p < 2; p++) {
            float4 v = *(const float4*)(pb + 4 * p);
            uint4 w = make_uint4(f2tf(v.x), f2tf(v.y), f2tf(v.z), f2tf(v.w));
            *(uint4*)&Bs[0][bi][be4 + 4 * p] = w;
        }
        __syncthreads();

        int s = 0;
        for (int t = 0; t < 32; t++) {
            float4 ra[2], rb[2];
            if (t < 31) {
                const float* qa = pa + (size_t)(t + 1) * 16 * UDIM;
                const float* qb = pb + (t + 1) * 16;
                #pragma unroll
                for (int p = 0; p < 2; p++)
                    ra[p] = *(const float4*)(qa + (size_t)(8 * p) * UDIM);
                #pragma unroll
                for (int p = 0; p < 2; p++)
                    rb[p] = *(const float4*)(qb + 4 * p);
            }

            #pragma unroll
            for (int k8 = 0; k8 < 2; k8++) {
                const int e0 = k8 * 8 + (lane & 3);
                unsigned a[4][4];
                #pragma unroll
                for (int mf = 0; mf < 4; mf++) {
                    int row = wu * 64 + mf * 16 + (lane >> 2);
                    a[mf][0] = As[s][e0    ][row    ];
                    a[mf][1] = As[s][e0    ][row + 8];
                    a[mf][2] = As[s][e0 + 4][row    ];
                    a[mf][3] = As[s][e0 + 4][row + 8];
                }
                unsigned bfr[4][2];
                #pragma unroll
                for (int nf = 0; nf < 4; nf++) {
                    int col = wi * 32 + nf * 8 + (lane >> 2);
                    bfr[nf][0] = Bs[s][col][e0    ];
                    bfr[nf][1] = Bs[s][col][e0 + 4];
                }
                #pragma unroll
                for (int mf = 0; mf < 4; mf++)
                    #pragma unroll
                    for (int nf = 0; nf < 4; nf++)
                        mma_tf32(c[mf][nf][0], c[mf][nf][1], c[mf][nf][2], c[mf][nf][3],
                                 a[mf][0], a[mf][1], a[mf][2], a[mf][3],
                                 bfr[nf][0], bfr[nf][1]);
            }

            if (t < 31) {
                #pragma unroll
                for (int p = 0; p < 2; p++) {
                    uint4 w = make_uint4(f2tf(ra[p].x), f2tf(ra[p].y),
                                         f2tf(ra[p].z), f2tf(ra[p].w));
                    *(uint4*)&As[s ^ 1][ae_ + 8 * p][au4] = w;
                }
                #pragma unroll
                for (int p = 0; p < 2; p++) {
                    uint4 w = make_uint4(f2tf(rb[p].x), f2tf(rb[p].y),
                                         f2tf(rb[p].z), f2tf(rb[p].w));
                    *(uint4*)&Bs[s ^ 1][bi][be4 + 4 * p] = w;
                }
            }
            __syncthreads();
            s ^= 1;
        }

        __half* outb = g_aeT + (size_t)b * UDIM * ENL;
        #pragma unroll
        for (int mf = 0; mf < 4; mf++) {
            const int ug = u0 + wu * 64 + mf * 16 + (lane >> 2);
            #pragma unroll
            for (int nf = 0; nf < 4; nf++) {
                const int ig = i0 + wi * 32 + nf * 8 + 2 * (lane & 3);
                *(unsigned*)(outb + (size_t)ug * ENL + ig) =
                    cvt_f16x2(c[mf][nf][0], c[mf][nf][1]);
                *(unsigned*)(outb + (size_t)(ug + 8) * ENL + ig) =
                    cvt_f16x2(c[mf][nf][2], c[mf][nf][3]);
            }
        }
    } else {
        const int u0 = (blockIdx.x - 16) * 64;
        __shared__ float Ac[16][68];
        __shared__ float Bc[16][68];
        __shared__ float tws[64];
        const float* deb = de + (size_t)b * DEL * EDIM;
        const int tj = tid & 15;
        const int tu = tid >> 4;
        ull acc2[4][2] = {};

        if (tid < 64) {
            float acc = 0.f;
            const float* wr = wt + (size_t)(u0 + tid) * TDIM;
            const float* tp = topics + b * TDIM;
            #pragma unroll 4
            for (int t = 0; t < TDIM; t++) acc = fmaf(tp[t], wr[t], acc);
            tws[tid] = acc;
        }

        for (int e0 = 0; e0 < EDIM; e0 += 16) {
            #pragma unroll
            for (int r = 0; r < 4; r++) {
                int l = tid + 256 * r;
                int e = l & 15, j = l >> 4;
                Ac[e][j] = deb[(size_t)j * EDIM + e0 + e];
            }
            #pragma unroll
            for (int r = 0; r < 4; r++) {
                int l = tid + 256 * r;
                int e = l >> 6, uu = l & 63;
                Bc[e][uu] = w_de[(size_t)(e0 + e) * UDIM + u0 + uu];
            }
            __syncthreads();
            #pragma unroll
            for (int k = 0; k < 16; k++) {
                const float4 av = *(const float4*)&Ac[k][tj * 4];
                const ull b01 = *(const ull*)&Bc[k][tu * 4];
                const ull b23 = *(const ull*)&Bc[k][tu * 4 + 2];
                ull pa0 = pack2(av.x, av.x), pa1 = pack2(av.y, av.y);
                ull pa2 = pack2(av.z, av.z), pa3 = pack2(av.w, av.w);
                acc2[0][0] = fma2(pa0, b01, acc2[0][0]); acc2[0][1] = fma2(pa0, b23, acc2[0][1]);
                acc2[1][0] = fma2(pa1, b01, acc2[1][0]); acc2[1][1] = fma2(pa1, b23, acc2[1][1]);
                acc2[2][0] = fma2(pa2, b01, acc2[2][0]); acc2[2][1] = fma2(pa2, b23, acc2[2][1]);
                acc2[3][0] = fma2(pa3, b01, acc2[3][0]); acc2[3][1] = fma2(pa3, b23, acc2[3][1]);
            }
            __syncthreads();
        }
        #pragma unroll
        for (int r = 0; r < 4; r++) {
            float2 v01, v23;
            unpack2(acc2[r][0], v01.x, v01.y);
            unpack2(acc2[r][1], v23.x, v23.y);
            int j = tj * 4 + r;
            float* row = g_c + ((size_t)b * DEL + j) * UDIM + u0 + tu * 4;
            row[0] = v01.x + tws[tu * 4 + 0];
            row[1] = v01.y + tws[tu * 4 + 1];
            row[2] = v23.x + tws[tu * 4 + 2];
            row[3] = v23.y + tws[tu * 4 + 3];
        }
    }
}

// ---------------------------------------------------------------------------
// Kernel 3 (fused attention): block = (b, j0..j0+1), 512 threads, 2 blocks/SM.
// Two 256-thread halves; half h owns j = j0+h; thread covers i = 2tq, 2tq+1
// via one half2 load. grid = (32, 8) = 256 blocks -> all SMs busy, phases of
// co-resident blocks overlap.
// ---------------------------------------------------------------------------
__global__ void __launch_bounds__(512, 2) k_attn(
    const float* __restrict__ en, const float* __restrict__ de,
    const float* __restrict__ nu, float* __restrict__ out)
{
    const int b    = blockIdx.y;
    const int j0   = blockIdx.x * 2;
    const int tid  = threadIdx.x;
    const int half = tid >> 8;          // 0..1 -> j = j0+half
    const int tq   = tid & 255;

    __shared__ uint2 css[2][UDIM];      // [h][u] = { half2(c,c), fp32 nu bits }
    __shared__ float alph_s[ENL][2];    // [i][h]
    __shared__ float redh[2][8];

    {
        const float* cb = g_c + ((size_t)b * DEL + j0 + half) * UDIM;
        #pragma unroll
        for (int uu = tq; uu < UDIM; uu += 256) {
            float cv = cb[uu];
            __half2 ch = __float2half2_rn(cv);
            css[half][uu] = make_uint2(*reinterpret_cast<unsigned*>(&ch),
                                       __float_as_uint(nu[uu]));
        }
    }
    __syncthreads();

    // Phase 1: mu for i = 2tq, 2tq+1 and j = j0+half. Pipelined half2 strips.
    const __half2* ae = reinterpret_cast<const __half2*>(
                            g_aeT + (size_t)b * UDIM * ENL) + tq;
    float m0 = 0.f, m1 = 0.f;
    {
        __half2 bufA[STRIP], bufB[STRIP];
        #pragma unroll
        for (int k = 0; k < STRIP; k++)
            bufA[k] = __ldg(ae + (size_t)k * (ENL / 2));

        #pragma unroll 1
        for (int u0 = 0; u0 < UDIM; u0 += 2 * STRIP) {
            #pragma unroll
            for (int k = 0; k < STRIP; k++)
                bufB[k] = __ldg(ae + (size_t)(u0 + STRIP + k) * (ENL / 2));
            #pragma unroll
            for (int k = 0; k < STRIP; k++) {
                uint2 cn = css[half][u0 + k];
                __half2 ch = *reinterpret_cast<__half2*>(&cn.x);
                float nv = __uint_as_float(cn.y);
                float2 tf = __half22float2(htanh2(__hadd2(bufA[k], ch)));
                m0 = fmaf(nv, tf.x, m0);
                m1 = fmaf(nv, tf.y, m1);
            }
            if (u0 + 2 * STRIP < UDIM) {
                #pragma unroll
                for (int k = 0; k < STRIP; k++)
                    bufA[k] = __ldg(ae + (size_t)(u0 + 2 * STRIP + k) * (ENL / 2));
            }
            #pragma unroll
            for (int k = 0; k < STRIP; k++) {
                uint2 cn = css[half][u0 + STRIP + k];
                __half2 ch = *reinterpret_cast<__half2*>(&cn.x);
                float nv = __uint_as_float(cn.y);
                float2 tf = __half22float2(htanh2(__hadd2(bufB[k], ch)));
                m0 = fmaf(nv, tf.x, m0);
                m1 = fmaf(nv, tf.y, m1);
            }
        }
    }

    // Softmax without max-subtraction (|mu| <= sum|nu| ~ 20, fp32-safe).
    float e0 = __expf(m0);
    float e1 = __expf(m1);

    // Sum over i within half: warp reduce, then 8 warps via smem.
    const int widh = tq >> 5, lane = tq & 31;
    float sum = e0 + e1;
    #pragma unroll
    for (int o = 16; o; o >>= 1)
        sum += __shfl_xor_sync(0xffffffffu, sum, o);
    if (lane == 0) redh[half][widh] = sum;
    __syncthreads();
    float S = redh[half][0];
    #pragma unroll
    for (int w = 1; w < 8; w++) S += redh[half][w];

    float inv = 1.f / S;
    float a0 = e0 * inv, a1 = e1 * inv;
    alph_s[2 * tq][half]     = a0;
    alph_s[2 * tq + 1][half] = a1;

    // Outputs for this half's j: alphas + p_gen (float2 contiguous stores)
    float* alphas_out = out + BSZ * DEL * ENL;
    float* pgen_out   = out + 2 * BSZ * DEL * ENL;
    const int base = ((b * DEL + j0 + half) * ENL) + 2 * tq;
    *(float2*)(alphas_out + base) = make_float2(a0, a1);
    *(float2*)(pgen_out + base) =
        make_float2(1.f / (1.f + __expf(-m0)), 1.f / (1.f + __expf(-m1)));
    __syncthreads();

    // Phase 2: thread owns e = tid for BOTH j's of the block.
    float s0 = 0.f, s1 = 0.f;
    const float* enb = en + (size_t)b * ENL * EDIM + tid;
    {
        float bufA[STRIP], bufB[STRIP];
        #pragma unroll
        for (int k = 0; k < STRIP; k++)
            bufA[k] = __ldg(enb + (size_t)k * EDIM);

        #pragma unroll 1
        for (int i0 = 0; i0 < ENL; i0 += 2 * STRIP) {
            #pragma unroll
            for (int k = 0; k < STRIP; k++)
                bufB[k] = __ldg(enb + (size_t)(i0 + STRIP + k) * EDIM);
            #pragma unroll
            for (int k = 0; k < STRIP; k++) {
                float2 av = *(const float2*)&alph_s[i0 + k][0];
                s0 = fmaf(av.x, bufA[k], s0);
                s1 = fmaf(av.y, bufA[k], s1);
            }
            if (i0 + 2 * STRIP < ENL) {
                #pragma unroll
                for (int k = 0; k < STRIP; k++)
                    bufA[k] = __ldg(enb + (size_t)(i0 + 2 * STRIP + k) * EDIM);
            }
            #pragma unroll
            for (int k = 0; k < STRIP; k++) {
                float2 av = *(const float2*)&alph_s[i0 + STRIP + k][0];
                s0 = fmaf(av.x, bufB[k], s0);
                s1 = fmaf(av.y, bufB[k], s1);
            }
        }
    }
    const int ob = ((b * DEL + j0) * EDIM) + tid;
    out[ob       ] = de[ob       ] + s0;
    out[ob + EDIM] = de[ob + EDIM] + s1;
}

// ---------------------------------------------------------------------------
extern "C" void kernel_launch(void* const* d_in, const int* in_sizes, int n_in,
                              void* d_out, int out_size)
{
    const float* en     = (const float*)d_in[0];
    const float* de     = (const float*)d_in[1];
    const float* topics = (const float*)d_in[2];
    const float* w_en   = (const float*)d_in[3];
    const float* w_de   = (const float*)d_in[4];
    const float* nu     = (const float*)d_in[5];
    const float* wt     = (const float*)d_in[6];
    float* out = (float*)d_out;

    k_gemm_c<<<dim3(24, BSZ), 256>>>(en, w_en, de, w_de, topics, wt);
    k_attn<<<dim3(DEL / 2, BSZ), 512>>>(en, de, nu, out);
}